// round 7
// baseline (speedup 1.0000x reference)
#include <cuda_runtime.h>
#include <math.h>
#include <stdint.h>

// Problem constants
#define BATCH 32
#define CDIM  256
#define HW    1024            // 32*32
#define NPOS  32768           // BATCH*HW
#define KCODE 1024
#define TOTAL 8388608         // BATCH*CDIM*HW

typedef unsigned long long ull;

// Scratch (device globals; no allocation allowed)
__device__ int           g_idx[NPOS];
__device__ float         g_wsq[KCODE];
__device__ float         g_zsq[NPOS];
__device__ unsigned int  g_counts[KCODE];
__device__ float         g_partial[1024];

// Packed fp32x2 FMA (Blackwell): two independent RN FMAs per instruction.
#define FMA2(d, a, b, c) \
    asm("fma.rn.f32x2 %0, %1, %2, %3;" : "=l"(d) : "l"(a), "l"(b), "l"(c))
#define PACK_DUP(d, s) \
    asm("mov.b64 %0, {%1, %1};" : "=l"(d) : "r"(__float_as_uint(s)))
#define UNPACK2(lo, hi, s) \
    asm("mov.b64 {%0, %1}, %2;" : "=f"(lo), "=f"(hi) : "l"(s))

// ---------------------------------------------------------------------------
__global__ void k_zero() {
    g_counts[threadIdx.x] = 0u;
}

// ---------------------------------------------------------------------------
__global__ __launch_bounds__(256) void k_wsq(const float* __restrict__ w) {
    int warp = (blockIdx.x * 256 + threadIdx.x) >> 5;   // 0..1023
    int lane = threadIdx.x & 31;
    const float* row = w + (size_t)warp * CDIM;
    float s = 0.f;
    #pragma unroll
    for (int j = 0; j < CDIM / 32; ++j) {
        float v = row[lane + j * 32];
        s = fmaf(v, v, s);
    }
    #pragma unroll
    for (int off = 16; off > 0; off >>= 1)
        s += __shfl_down_sync(0xFFFFFFFFu, s, off);
    if (lane == 0) g_wsq[warp] = s;
}

// ---------------------------------------------------------------------------
__global__ __launch_bounds__(256) void k_zsq(const float* __restrict__ z) {
    __shared__ float sm[256][33];   // [channel][position], padded
    const int t   = threadIdx.x;
    const int n0  = blockIdx.x * 32;
    const int b   = n0 >> 10;
    const int hw0 = n0 & 1023;
    const float* zb = z + (size_t)b * (CDIM * HW) + hw0;

    #pragma unroll 8
    for (int it = 0; it < 32; ++it) {
        int idx = it * 256 + t;
        int c = idx >> 5, hwi = idx & 31;
        sm[c][hwi] = zb[(size_t)c * HW + hwi];
    }
    __syncthreads();

    const int wrp = t >> 5, lane = t & 31;
    for (int r = 0; r < 4; ++r) {
        const int hwi = wrp * 4 + r;
        float acc = 0.f;
        #pragma unroll
        for (int i = 0; i < 8; ++i) {
            float a = sm[32 * i + lane][hwi];
            acc = __fadd_rn(acc, __fmul_rn(a, a));
        }
        #pragma unroll
        for (int off = 16; off > 0; off >>= 1)
            acc = __fadd_rn(acc, __shfl_down_sync(0xFFFFFFFFu, acc, off));
        if (lane == 0) g_zsq[n0 + hwi] = acc;
    }
}

// ---------------------------------------------------------------------------
// Kernel A: fused fp32 GEMM + argmin, fp32x2 FMA.
//  - 128 pos x 128 codes per block; 8 pos x 8 codes per thread.
//  - w staged PRE-DUPLICATED as {w,w} ull -> hot loop has NO pack movs:
//      6 LDS.128 + 32 FMA2 per cc.
//  - ping-pong smem buffers, register-staged prefetch (LDG at chunk top,
//    STS after compute), ONE __syncthreads per chunk.
// acc chains are exact ascending-c scalar-RN FMA chains; dist bits match:
//   dist = RN( RN(zsq - 2*m) + wsq ), argmin ties -> lowest index.
// ---------------------------------------------------------------------------
__global__ __launch_bounds__(256, 2) void k_argmin(const float* __restrict__ z,
                                                   const float* __restrict__ w) {
    __shared__ float zs[2][16][128];
    __shared__ ull   ws2[2][16][128];
    __shared__ ull   bests[128];

    const int t  = threadIdx.x;
    const int tx = t & 15;       // position group
    const int ty = t >> 4;       // code group

    const int n0  = blockIdx.x * 128;
    const int b   = n0 >> 10;
    const int hw0 = n0 & 1023;
    const float* zbase = z + (size_t)b * (CDIM * HW) + hw0;

    // staging indices
    const int zc = t >> 5;            // 0..7 (two z rows per thread: zc, zc+8)
    const int zp = (t & 31) * 4;      // 0..124
    const int wk = t >> 1;            // 0..127 (code)
    const int wq = (t & 1) * 8;       // 0 or 8 (channel offset)

    const float* zsrcA = zbase + (size_t)zc * HW + zp;        // + c0*HW per ct
    const float* zsrcB = zbase + (size_t)(8 + zc) * HW + zp;
    const float* wsrc  = w + (size_t)wk * CDIM + wq;          // + nk0*CDIM + nc0

    float zsqv[8];
    #pragma unroll
    for (int i = 0; i < 4; ++i) {
        zsqv[i]     = g_zsq[n0 + tx * 4 + i];
        zsqv[4 + i] = g_zsq[n0 + 64 + tx * 4 + i];
    }

    float bestv[8];
    int   bestk[8];
    #pragma unroll
    for (int i = 0; i < 8; ++i) { bestv[i] = 3.4e38f; bestk[i] = 0; }

    // ---- stage chunk 0 into buffer 0 ----
    {
        float4 zr0 = *(const float4*)zsrcA;
        float4 zr1 = *(const float4*)zsrcB;
        float4 wr0 = *(const float4*)wsrc;
        float4 wr1 = *(const float4*)(wsrc + 4);
        *(float4*)&zs[0][zc][zp]     = zr0;
        *(float4*)&zs[0][8 + zc][zp] = zr1;
        ull r;
        PACK_DUP(r, wr0.x); ws2[0][wq + 0][wk] = r;
        PACK_DUP(r, wr0.y); ws2[0][wq + 1][wk] = r;
        PACK_DUP(r, wr0.z); ws2[0][wq + 2][wk] = r;
        PACK_DUP(r, wr0.w); ws2[0][wq + 3][wk] = r;
        PACK_DUP(r, wr1.x); ws2[0][wq + 4][wk] = r;
        PACK_DUP(r, wr1.y); ws2[0][wq + 5][wk] = r;
        PACK_DUP(r, wr1.z); ws2[0][wq + 6][wk] = r;
        PACK_DUP(r, wr1.w); ws2[0][wq + 7][wk] = r;
    }
    __syncthreads();

    int p = 0;
    for (int kt = 0; kt < KCODE / 128; ++kt) {
        const int k0 = kt * 128;
        ull acc2[4][8];
        #pragma unroll
        for (int i = 0; i < 4; ++i)
            #pragma unroll
            for (int j = 0; j < 8; ++j) acc2[i][j] = 0ull;

        for (int ct = 0; ct < 16; ++ct) {
            const int nxt = kt * 16 + ct + 1;
            const bool pre = (nxt < 128);
            float4 zr0, zr1, wr0, wr1;
            if (pre) {
                const int nc0 = (nxt & 15) << 4;      // next channel offset
                const int nk0 = (nxt >> 4) << 7;      // next code offset
                zr0 = *(const float4*)(zsrcA + (size_t)nc0 * HW);
                zr1 = *(const float4*)(zsrcB + (size_t)nc0 * HW);
                const float* wp = wsrc + (size_t)nk0 * CDIM + nc0;
                wr0 = *(const float4*)wp;
                wr1 = *(const float4*)(wp + 4);
            }

            // ---- compute 16 cc on buffer p: 6 LDS.128 + 32 FMA2 each ----
            #pragma unroll
            for (int cc = 0; cc < 16; ++cc) {
                ulonglong2 za  = *(const ulonglong2*)&zs[p][cc][tx * 4];
                ulonglong2 zb2 = *(const ulonglong2*)&zs[p][cc][64 + tx * 4];
                ulonglong2 wa  = *(const ulonglong2*)&ws2[p][cc][ty * 4];
                ulonglong2 wa2 = *(const ulonglong2*)&ws2[p][cc][ty * 4 + 2];
                ulonglong2 wb  = *(const ulonglong2*)&ws2[p][cc][64 + ty * 4];
                ulonglong2 wb2 = *(const ulonglong2*)&ws2[p][cc][64 + ty * 4 + 2];
                ull wd[8];
                wd[0] = wa.x;  wd[1] = wa.y;  wd[2] = wa2.x; wd[3] = wa2.y;
                wd[4] = wb.x;  wd[5] = wb.y;  wd[6] = wb2.x; wd[7] = wb2.y;
                #pragma unroll
                for (int j = 0; j < 8; ++j) {
                    FMA2(acc2[0][j], za.x,  wd[j], acc2[0][j]);
                    FMA2(acc2[1][j], za.y,  wd[j], acc2[1][j]);
                    FMA2(acc2[2][j], zb2.x, wd[j], acc2[2][j]);
                    FMA2(acc2[3][j], zb2.y, wd[j], acc2[3][j]);
                }
            }

            if (pre) {
                const int np = p ^ 1;
                *(float4*)&zs[np][zc][zp]     = zr0;
                *(float4*)&zs[np][8 + zc][zp] = zr1;
                ull r;
                PACK_DUP(r, wr0.x); ws2[np][wq + 0][wk] = r;
                PACK_DUP(r, wr0.y); ws2[np][wq + 1][wk] = r;
                PACK_DUP(r, wr0.z); ws2[np][wq + 2][wk] = r;
                PACK_DUP(r, wr0.w); ws2[np][wq + 3][wk] = r;
                PACK_DUP(r, wr1.x); ws2[np][wq + 4][wk] = r;
                PACK_DUP(r, wr1.y); ws2[np][wq + 5][wk] = r;
                PACK_DUP(r, wr1.z); ws2[np][wq + 6][wk] = r;
                PACK_DUP(r, wr1.w); ws2[np][wq + 7][wk] = r;
                __syncthreads();
                p = np;
            }
        }

        // epilogue: dist = RN( RN(zsq - 2*m) + wsq ), ascending k per thread
        #pragma unroll
        for (int j = 0; j < 8; ++j) {
            const int k = k0 + ((j < 4) ? (ty * 4 + j) : (64 + ty * 4 + (j - 4)));
            const float wsq = g_wsq[k];
            #pragma unroll
            for (int i2 = 0; i2 < 4; ++i2) {
                float m0, m1;
                UNPACK2(m0, m1, acc2[i2][j]);
                const int ia = i2 * 2;          // best-slot index (0..7)
                const float zsqA = (i2 < 2) ? zsqv[i2 * 2]     : zsqv[4 + (i2 - 2) * 2];
                const float zsqB = (i2 < 2) ? zsqv[i2 * 2 + 1] : zsqv[4 + (i2 - 2) * 2 + 1];
                float t1a = fmaf(-2.0f, m0, zsqA);
                float sca = __fadd_rn(t1a, wsq);
                if (sca < bestv[ia]) { bestv[ia] = sca; bestk[ia] = k; }
                float t1b = fmaf(-2.0f, m1, zsqB);
                float scb = __fadd_rn(t1b, wsq);
                if (scb < bestv[ia + 1]) { bestv[ia + 1] = scb; bestk[ia + 1] = k; }
            }
        }
    }

    if (t < 128) bests[t] = ~0ull;
    __syncthreads();
    #pragma unroll
    for (int i = 0; i < 8; ++i) {
        const int i2 = i >> 1;
        const int lp = (i2 < 2) ? (tx * 4 + i2 * 2 + (i & 1))
                                : (64 + tx * 4 + (i2 - 2) * 2 + (i & 1));
        unsigned u = __float_as_uint(bestv[i]);
        u = (u & 0x80000000u) ? ~u : (u | 0x80000000u);   // order-preserving map
        ull e = ((ull)u << 32) | (unsigned)bestk[i];
        atomicMin(&bests[lp], e);
    }
    __syncthreads();
    if (t < 128) {
        int idx = (int)(bests[t] & 0xFFFFFFFFull);
        g_idx[n0 + t] = idx;
        atomicAdd(&g_counts[idx], 1u);
    }
}

// ---------------------------------------------------------------------------
// Kernel B: gather codebook, straight-through output, squared-diff partials.
// ---------------------------------------------------------------------------
__global__ __launch_bounds__(256) void k_quant(const float* __restrict__ z,
                                               const float* __restrict__ w,
                                               float* __restrict__ out) {
    __shared__ float sm[256];
    float local = 0.f;
    for (int i4 = blockIdx.x * 256 + threadIdx.x; i4 < TOTAL / 4; i4 += 1024 * 256) {
        const int i  = i4 * 4;
        const int hw = i & 1023;
        const int c  = (i >> 10) & 255;
        const int b  = i >> 18;
        const int* ib = &g_idx[b * HW + hw];
        float4 zz = *(const float4*)(z + i);
        float q0 = w[(size_t)ib[0] * CDIM + c];
        float q1 = w[(size_t)ib[1] * CDIM + c];
        float q2 = w[(size_t)ib[2] * CDIM + c];
        float q3 = w[(size_t)ib[3] * CDIM + c];
        float4 o;
        float d;
        d = __fadd_rn(q0, -zz.x); o.x = __fadd_rn(zz.x, d); local = fmaf(d, d, local);
        d = __fadd_rn(q1, -zz.y); o.y = __fadd_rn(zz.y, d); local = fmaf(d, d, local);
        d = __fadd_rn(q2, -zz.z); o.z = __fadd_rn(zz.z, d); local = fmaf(d, d, local);
        d = __fadd_rn(q3, -zz.w); o.w = __fadd_rn(zz.w, d); local = fmaf(d, d, local);
        *(float4*)(out + i) = o;
    }
    sm[threadIdx.x] = local;
    __syncthreads();
    for (int s = 128; s > 0; s >>= 1) {
        if (threadIdx.x < s) sm[threadIdx.x] += sm[threadIdx.x + s];
        __syncthreads();
    }
    if (threadIdx.x == 0) g_partial[blockIdx.x] = sm[0];
}

// ---------------------------------------------------------------------------
__global__ __launch_bounds__(1024) void k_final(float* __restrict__ out) {
    __shared__ float sm[1024];
    const int t = threadIdx.x;

    sm[t] = g_partial[t];
    __syncthreads();
    for (int s = 512; s > 0; s >>= 1) {
        if (t < s) sm[t] += sm[t + s];
        __syncthreads();
    }
    if (t == 0) {
        float m = sm[0] / (float)TOTAL;
        out[TOTAL] = m + 0.25f * m;      // q_latent + COMMITMENT_COST * e_latent
    }
    __syncthreads();

    float p = (float)g_counts[t] * (1.0f / (float)NPOS);
    sm[t] = p * logf(p + 1e-10f);
    __syncthreads();
    for (int s = 512; s > 0; s >>= 1) {
        if (t < s) sm[t] += sm[t + s];
        __syncthreads();
    }
    if (t == 0) out[TOTAL + 1] = expf(-sm[0]);
}

// ---------------------------------------------------------------------------
extern "C" void kernel_launch(void* const* d_in, const int* in_sizes, int n_in,
                              void* d_out, int out_size) {
    const float* z = (const float*)d_in[0];
    const float* w = (const float*)d_in[1];
    float* out = (float*)d_out;

    k_zero<<<1, 1024>>>();
    k_wsq<<<128, 256>>>(w);
    k_zsq<<<NPOS / 32, 256>>>(z);
    k_argmin<<<NPOS / 128, 256>>>(z, w);
    k_quant<<<1024, 256>>>(z, w, out);
    k_final<<<1, 1024>>>(out);
}

// round 8
// speedup vs baseline: 1.2157x; 1.2157x over previous
#include <cuda_runtime.h>
#include <math.h>
#include <stdint.h>

// Problem constants
#define BATCH 32
#define CDIM  256
#define HW    1024            // 32*32
#define NPOS  32768           // BATCH*HW
#define KCODE 1024
#define TOTAL 8388608         // BATCH*CDIM*HW

typedef unsigned long long ull;

// Scratch (device globals; no allocation allowed)
__device__ int           g_idx[NPOS];
__device__ float         g_wsq[KCODE];
__device__ float         g_zsq[NPOS];
__device__ unsigned int  g_counts[KCODE];
__device__ float         g_partial[1024];

// Packed fp32x2 FMA (Blackwell): two independent RN FMAs per instruction.
#define FMA2(d, a, b, c) \
    asm("fma.rn.f32x2 %0, %1, %2, %3;" : "=l"(d) : "l"(a), "l"(b), "l"(c))
#define PACK_DUP(d, s) \
    asm("mov.b64 %0, {%1, %1};" : "=l"(d) : "r"(__float_as_uint(s)))
#define UNPACK2(lo, hi, s) \
    asm("mov.b64 {%0, %1}, %2;" : "=f"(lo), "=f"(hi) : "l"(s))

#define CP_ASYNC16(dst_u32, src_ptr) \
    asm volatile("cp.async.ca.shared.global [%0], [%1], 16;" :: "r"(dst_u32), "l"(src_ptr))
#define CP_COMMIT() asm volatile("cp.async.commit_group;")
#define CP_WAIT0()  asm volatile("cp.async.wait_group 0;")

// ---------------------------------------------------------------------------
__global__ void k_zero() {
    g_counts[threadIdx.x] = 0u;
}

// ---------------------------------------------------------------------------
__global__ __launch_bounds__(256) void k_wsq(const float* __restrict__ w) {
    int warp = (blockIdx.x * 256 + threadIdx.x) >> 5;   // 0..1023
    int lane = threadIdx.x & 31;
    const float* row = w + (size_t)warp * CDIM;
    float s = 0.f;
    #pragma unroll
    for (int j = 0; j < CDIM / 32; ++j) {
        float v = row[lane + j * 32];
        s = fmaf(v, v, s);
    }
    #pragma unroll
    for (int off = 16; off > 0; off >>= 1)
        s += __shfl_down_sync(0xFFFFFFFFu, s, off);
    if (lane == 0) g_wsq[warp] = s;
}

// ---------------------------------------------------------------------------
__global__ __launch_bounds__(256) void k_zsq(const float* __restrict__ z) {
    __shared__ float sm[256][33];   // [channel][position], padded
    const int t   = threadIdx.x;
    const int n0  = blockIdx.x * 32;
    const int b   = n0 >> 10;
    const int hw0 = n0 & 1023;
    const float* zb = z + (size_t)b * (CDIM * HW) + hw0;

    #pragma unroll 8
    for (int it = 0; it < 32; ++it) {
        int idx = it * 256 + t;
        int c = idx >> 5, hwi = idx & 31;
        sm[c][hwi] = zb[(size_t)c * HW + hwi];
    }
    __syncthreads();

    const int wrp = t >> 5, lane = t & 31;
    for (int r = 0; r < 4; ++r) {
        const int hwi = wrp * 4 + r;
        float acc = 0.f;
        #pragma unroll
        for (int i = 0; i < 8; ++i) {
            float a = sm[32 * i + lane][hwi];
            acc = __fadd_rn(acc, __fmul_rn(a, a));
        }
        #pragma unroll
        for (int off = 16; off > 0; off >>= 1)
            acc = __fadd_rn(acc, __shfl_down_sync(0xFFFFFFFFu, acc, off));
        if (lane == 0) g_zsq[n0 + hwi] = acc;
    }
}

// ---------------------------------------------------------------------------
// Kernel A: fused fp32 GEMM + argmin, fp32x2 FMA.
//  - 128 pos x 128 codes per block; 8 pos x 8 codes per thread.
//  - HOT LOOP IDENTICAL TO R5: 4 LDS.128 + 8 PACK + 32 FMA2 per cc.
//  - pipelined staging: z chunk -> cp.async into idle buffer (issued before
//    compute), w chunk -> LDG regs before compute, STS after compute.
//    ONE __syncthreads per chunk.
// acc chains are exact ascending-c scalar-RN FMA chains; dist bits match:
//   dist = RN( RN(zsq - 2*m) + wsq ), argmin ties -> lowest index.
// ---------------------------------------------------------------------------
__global__ __launch_bounds__(256, 2) void k_argmin(const float* __restrict__ z,
                                                   const float* __restrict__ w) {
    __shared__ float zs[2][16][128];
    __shared__ float ws[2][16][128];
    __shared__ ull   bests[128];

    const int t  = threadIdx.x;
    const int tx = t & 15;       // position group
    const int ty = t >> 4;       // code group

    const int n0  = blockIdx.x * 128;
    const int b   = n0 >> 10;
    const int hw0 = n0 & 1023;
    const float* zbase = z + (size_t)b * (CDIM * HW) + hw0;

    // staging indices
    const int zc = t >> 5;            // 0..7 (two z rows per thread: zc, zc+8)
    const int zp = (t & 31) * 4;      // 0..124
    const int wk = t >> 1;            // 0..127 (code)
    const int wq = (t & 1) * 8;       // 0 or 8 (channel offset)

    const float* zsrcA = zbase + (size_t)zc * HW + zp;        // + c0*HW per ct
    const float* zsrcB = zbase + (size_t)(8 + zc) * HW + zp;
    const float* wsrc  = w + (size_t)wk * CDIM + wq;          // + nk0*CDIM + nc0

    // cp.async shared destinations (computed once)
    const unsigned zd[2][2] = {
        { (unsigned)__cvta_generic_to_shared(&zs[0][zc][zp]),
          (unsigned)__cvta_generic_to_shared(&zs[0][8 + zc][zp]) },
        { (unsigned)__cvta_generic_to_shared(&zs[1][zc][zp]),
          (unsigned)__cvta_generic_to_shared(&zs[1][8 + zc][zp]) }
    };

    float zsqv[8];
    #pragma unroll
    for (int i = 0; i < 4; ++i) {
        zsqv[i]     = g_zsq[n0 + tx * 4 + i];
        zsqv[4 + i] = g_zsq[n0 + 64 + tx * 4 + i];
    }

    float bestv[8];
    int   bestk[8];
    #pragma unroll
    for (int i = 0; i < 8; ++i) { bestv[i] = 3.4e38f; bestk[i] = 0; }

    // ---- stage chunk 0 into buffer 0 ----
    {
        CP_ASYNC16(zd[0][0], zsrcA);
        CP_ASYNC16(zd[0][1], zsrcB);
        CP_COMMIT();
        float4 wr0 = *(const float4*)wsrc;
        float4 wr1 = *(const float4*)(wsrc + 4);
        ws[0][wq + 0][wk] = wr0.x;
        ws[0][wq + 1][wk] = wr0.y;
        ws[0][wq + 2][wk] = wr0.z;
        ws[0][wq + 3][wk] = wr0.w;
        ws[0][wq + 4][wk] = wr1.x;
        ws[0][wq + 5][wk] = wr1.y;
        ws[0][wq + 6][wk] = wr1.z;
        ws[0][wq + 7][wk] = wr1.w;
        CP_WAIT0();
    }
    __syncthreads();

    int p = 0;
    for (int kt = 0; kt < KCODE / 128; ++kt) {
        const int k0 = kt * 128;
        ull acc2[4][8];
        #pragma unroll
        for (int i = 0; i < 4; ++i)
            #pragma unroll
            for (int j = 0; j < 8; ++j) acc2[i][j] = 0ull;

        for (int ct = 0; ct < 16; ++ct) {
            const int nxt = kt * 16 + ct + 1;
            const bool pre = (nxt < 128);
            float4 wr0, wr1;
            if (pre) {
                const int nc0 = (nxt & 15) << 4;      // next channel offset
                const int nk0 = (nxt >> 4) << 7;      // next code offset
                const int np = p ^ 1;
                CP_ASYNC16(zd[np][0], zsrcA + (size_t)nc0 * HW);
                CP_ASYNC16(zd[np][1], zsrcB + (size_t)nc0 * HW);
                CP_COMMIT();
                const float* wp = wsrc + (size_t)nk0 * CDIM + nc0;
                wr0 = *(const float4*)wp;
                wr1 = *(const float4*)(wp + 4);
            }

            // ---- R5 hot loop, verbatim: 4 LDS.128 + 8 PACK + 32 FMA2 ----
            #pragma unroll
            for (int cc = 0; cc < 16; ++cc) {
                ulonglong2 za  = *(const ulonglong2*)&zs[p][cc][tx * 4];
                ulonglong2 zb2 = *(const ulonglong2*)&zs[p][cc][64 + tx * 4];
                float4 wa = *(const float4*)&ws[p][cc][ty * 4];
                float4 wb = *(const float4*)&ws[p][cc][64 + ty * 4];
                ull wd[8];
                PACK_DUP(wd[0], wa.x); PACK_DUP(wd[1], wa.y);
                PACK_DUP(wd[2], wa.z); PACK_DUP(wd[3], wa.w);
                PACK_DUP(wd[4], wb.x); PACK_DUP(wd[5], wb.y);
                PACK_DUP(wd[6], wb.z); PACK_DUP(wd[7], wb.w);
                #pragma unroll
                for (int j = 0; j < 8; ++j) {
                    FMA2(acc2[0][j], za.x,  wd[j], acc2[0][j]);
                    FMA2(acc2[1][j], za.y,  wd[j], acc2[1][j]);
                    FMA2(acc2[2][j], zb2.x, wd[j], acc2[2][j]);
                    FMA2(acc2[3][j], zb2.y, wd[j], acc2[3][j]);
                }
            }

            if (pre) {
                const int np = p ^ 1;
                ws[np][wq + 0][wk] = wr0.x;
                ws[np][wq + 1][wk] = wr0.y;
                ws[np][wq + 2][wk] = wr0.z;
                ws[np][wq + 3][wk] = wr0.w;
                ws[np][wq + 4][wk] = wr1.x;
                ws[np][wq + 5][wk] = wr1.y;
                ws[np][wq + 6][wk] = wr1.z;
                ws[np][wq + 7][wk] = wr1.w;
                CP_WAIT0();
                __syncthreads();
                p = np;
            }
        }

        // epilogue: dist = RN( RN(zsq - 2*m) + wsq ), ascending k per thread
        #pragma unroll
        for (int j = 0; j < 8; ++j) {
            const int k = k0 + ((j < 4) ? (ty * 4 + j) : (64 + ty * 4 + (j - 4)));
            const float wsq = g_wsq[k];
            #pragma unroll
            for (int i2 = 0; i2 < 4; ++i2) {
                float m0, m1;
                UNPACK2(m0, m1, acc2[i2][j]);
                const int ia = i2 * 2;          // best-slot index (0..7)
                const float zsqA = (i2 < 2) ? zsqv[i2 * 2]     : zsqv[4 + (i2 - 2) * 2];
                const float zsqB = (i2 < 2) ? zsqv[i2 * 2 + 1] : zsqv[4 + (i2 - 2) * 2 + 1];
                float t1a = fmaf(-2.0f, m0, zsqA);
                float sca = __fadd_rn(t1a, wsq);
                if (sca < bestv[ia]) { bestv[ia] = sca; bestk[ia] = k; }
                float t1b = fmaf(-2.0f, m1, zsqB);
                float scb = __fadd_rn(t1b, wsq);
                if (scb < bestv[ia + 1]) { bestv[ia + 1] = scb; bestk[ia + 1] = k; }
            }
        }
    }

    if (t < 128) bests[t] = ~0ull;
    __syncthreads();
    #pragma unroll
    for (int i = 0; i < 8; ++i) {
        const int i2 = i >> 1;
        const int lp = (i2 < 2) ? (tx * 4 + i2 * 2 + (i & 1))
                                : (64 + tx * 4 + (i2 - 2) * 2 + (i & 1));
        unsigned u = __float_as_uint(bestv[i]);
        u = (u & 0x80000000u) ? ~u : (u | 0x80000000u);   // order-preserving map
        ull e = ((ull)u << 32) | (unsigned)bestk[i];
        atomicMin(&bests[lp], e);
    }
    __syncthreads();
    if (t < 128) {
        int idx = (int)(bests[t] & 0xFFFFFFFFull);
        g_idx[n0 + t] = idx;
        atomicAdd(&g_counts[idx], 1u);
    }
}

// ---------------------------------------------------------------------------
// Kernel B: gather codebook, straight-through output, squared-diff partials.
// ---------------------------------------------------------------------------
__global__ __launch_bounds__(256) void k_quant(const float* __restrict__ z,
                                               const float* __restrict__ w,
                                               float* __restrict__ out) {
    __shared__ float sm[256];
    float local = 0.f;
    for (int i4 = blockIdx.x * 256 + threadIdx.x; i4 < TOTAL / 4; i4 += 1024 * 256) {
        const int i  = i4 * 4;
        const int hw = i & 1023;
        const int c  = (i >> 10) & 255;
        const int b  = i >> 18;
        const int* ib = &g_idx[b * HW + hw];
        float4 zz = *(const float4*)(z + i);
        float q0 = w[(size_t)ib[0] * CDIM + c];
        float q1 = w[(size_t)ib[1] * CDIM + c];
        float q2 = w[(size_t)ib[2] * CDIM + c];
        float q3 = w[(size_t)ib[3] * CDIM + c];
        float4 o;
        float d;
        d = __fadd_rn(q0, -zz.x); o.x = __fadd_rn(zz.x, d); local = fmaf(d, d, local);
        d = __fadd_rn(q1, -zz.y); o.y = __fadd_rn(zz.y, d); local = fmaf(d, d, local);
        d = __fadd_rn(q2, -zz.z); o.z = __fadd_rn(zz.z, d); local = fmaf(d, d, local);
        d = __fadd_rn(q3, -zz.w); o.w = __fadd_rn(zz.w, d); local = fmaf(d, d, local);
        *(float4*)(out + i) = o;
    }
    sm[threadIdx.x] = local;
    __syncthreads();
    for (int s = 128; s > 0; s >>= 1) {
        if (threadIdx.x < s) sm[threadIdx.x] += sm[threadIdx.x + s];
        __syncthreads();
    }
    if (threadIdx.x == 0) g_partial[blockIdx.x] = sm[0];
}

// ---------------------------------------------------------------------------
__global__ __launch_bounds__(1024) void k_final(float* __restrict__ out) {
    __shared__ float sm[1024];
    const int t = threadIdx.x;

    sm[t] = g_partial[t];
    __syncthreads();
    for (int s = 512; s > 0; s >>= 1) {
        if (t < s) sm[t] += sm[t + s];
        __syncthreads();
    }
    if (t == 0) {
        float m = sm[0] / (float)TOTAL;
        out[TOTAL] = m + 0.25f * m;      // q_latent + COMMITMENT_COST * e_latent
    }
    __syncthreads();

    float p = (float)g_counts[t] * (1.0f / (float)NPOS);
    sm[t] = p * logf(p + 1e-10f);
    __syncthreads();
    for (int s = 512; s > 0; s >>= 1) {
        if (t < s) sm[t] += sm[t + s];
        __syncthreads();
    }
    if (t == 0) out[TOTAL + 1] = expf(-sm[0]);
}

// ---------------------------------------------------------------------------
extern "C" void kernel_launch(void* const* d_in, const int* in_sizes, int n_in,
                              void* d_out, int out_size) {
    const float* z = (const float*)d_in[0];
    const float* w = (const float*)d_in[1];
    float* out = (float*)d_out;

    k_zero<<<1, 1024>>>();
    k_wsq<<<128, 256>>>(w);
    k_zsq<<<NPOS / 32, 256>>>(z);
    k_argmin<<<NPOS / 128, 256>>>(z, w);
    k_quant<<<1024, 256>>>(z, w, out);
    k_final<<<1, 1024>>>(out);
}